// round 3
// baseline (speedup 1.0000x reference)
#include <cuda_runtime.h>
#include <cstdint>

#define DD 1024
#define NCTA 128
#define NTHREADS 1024
#define FMAX 1024

// Persistent state (no allocs allowed)
__device__ __align__(16) float g_v[2][DD];
__device__ unsigned g_count = 0;
__device__ unsigned g_gen = 0;

__device__ __forceinline__ void grid_barrier() {
    __syncthreads();
    if (threadIdx.x == 0) {
        __threadfence();
        unsigned gen = *((volatile unsigned*)&g_gen);
        unsigned t = atomicAdd(&g_count, 1u);
        if (t == NCTA - 1) {
            atomicExch(&g_count, 0u);
            __threadfence();
            atomicAdd(&g_gen, 1u);
        } else {
            while (*((volatile unsigned*)&g_gen) == gen) { }
        }
        __threadfence();
    }
    __syncthreads();
}

struct StepCtx {
    const int* sh_x;
    const float* core;
    const float* left;
    float (*sh_p)[9];
    int w, lane, colbase, col, rowbase, F;
};

// One chain step. m holds this step's matrix column-slice; after use it is
// refilled with step s+2's slice (prefetch issued before the barrier so the
// L2 latency hides under sync).
__device__ __forceinline__ void do_step(int s, float (&m)[8], const StepCtx& c) {
    // v fragment: 8 consecutive floats (rows rowbase..rowbase+8)
    float vv[8];
    if (s == 0) {
        float4 a = *(const float4*)(c.left + c.rowbase);
        float4 b = *(const float4*)(c.left + c.rowbase + 4);
        vv[0]=a.x; vv[1]=a.y; vv[2]=a.z; vv[3]=a.w;
        vv[4]=b.x; vv[5]=b.y; vv[6]=b.z; vv[7]=b.w;
    } else {
        const float4* vp = (const float4*)(g_v[(s + 1) & 1] + c.rowbase);
        float4 a = __ldcg(vp);
        float4 b = __ldcg(vp + 1);
        vv[0]=a.x; vv[1]=a.y; vv[2]=a.z; vv[3]=a.w;
        vv[4]=b.x; vv[5]=b.y; vv[6]=b.z; vv[7]=b.w;
    }

    float acc0 = 0.f, acc1 = 0.f;
    #pragma unroll
    for (int k = 0; k < 4; ++k) {
        acc0 = fmaf(m[k],     vv[k],     acc0);
        acc1 = fmaf(m[k + 4], vv[k + 4], acc1);
    }
    float acc = acc0 + acc1;

    // Prefetch step s+2's matrix slice into m (off critical path)
    {
        int sn = (s + 2 < c.F) ? (s + 2) : (c.F - 1);
        const float* Mn = c.core + (size_t)c.sh_x[sn] * (DD * DD);
        #pragma unroll
        for (int k = 0; k < 8; ++k)
            m[k] = __ldg(Mn + (size_t)(c.rowbase + k) * DD + c.col);
    }

    // Warp reduce over the 4 row-groups (lanes differing by 8,16)
    acc += __shfl_xor_sync(0xffffffffu, acc, 8);
    acc += __shfl_xor_sync(0xffffffffu, acc, 16);
    if (c.lane < 8) c.sh_p[c.w][c.lane] = acc;
    __syncthreads();

    // Warp 0: 32 warp-partials per column, 8 per lane, conflict-free (pad 9)
    if (c.w == 0) {
        int cc = c.lane & 7;
        int g  = c.lane >> 3;
        float t = 0.f;
        #pragma unroll
        for (int j = 0; j < 8; ++j) t += c.sh_p[g * 8 + j][cc];
        t += __shfl_xor_sync(0xffffffffu, t, 8);
        t += __shfl_xor_sync(0xffffffffu, t, 16);
        if (c.lane < 8) g_v[s & 1][c.colbase + c.lane] = t;
    }

    grid_barrier();
}

__global__ __launch_bounds__(NTHREADS, 1)
void tn_chain_kernel(const int* __restrict__ x,
                     const float* __restrict__ core,
                     const float* __restrict__ left,
                     const float* __restrict__ right,
                     float* __restrict__ out,
                     int F) {
    __shared__ int   sh_x[FMAX];
    __shared__ float sh_p[32][9];
    __shared__ float sh_r[32];

    const int tid  = threadIdx.x;
    const int w    = tid >> 5;
    const int lane = tid & 31;
    const int c    = lane & 7;          // column within CTA's 8
    const int r    = lane >> 3;         // row-group within warp
    const int colbase = blockIdx.x * 8;
    const int col  = colbase + c;
    const int rowbase = w * 32 + r * 8; // 8 consecutive rows per thread

    for (int i = tid; i < F; i += NTHREADS) sh_x[i] = x[i];
    __syncthreads();

    StepCtx ctx;
    ctx.sh_x = sh_x; ctx.core = core; ctx.left = left;
    ctx.sh_p = sh_p;
    ctx.w = w; ctx.lane = lane; ctx.colbase = colbase; ctx.col = col;
    ctx.rowbase = rowbase; ctx.F = F;

    // Prime 2-deep prefetch
    float m0[8], m1[8];
    {
        const float* M0 = core + (size_t)sh_x[0] * (DD * DD);
        #pragma unroll
        for (int k = 0; k < 8; ++k)
            m0[k] = __ldg(M0 + (size_t)(rowbase + k) * DD + col);
        const float* M1 = core + (size_t)sh_x[(F > 1) ? 1 : 0] * (DD * DD);
        #pragma unroll
        for (int k = 0; k < 8; ++k)
            m1[k] = __ldg(M1 + (size_t)(rowbase + k) * DD + col);
    }

    // F is even (1024); process two steps per iteration so m0/m1 stay in regs
    for (int s = 0; s < F; s += 2) {
        do_step(s,     m0, ctx);
        do_step(s + 1, m1, ctx);
    }

    // Final dot product: CTA 0 only, deterministic order
    if (blockIdx.x == 0) {
        float val = __ldcg(&g_v[(F - 1) & 1][tid]) * __ldg(right + tid);
        val += __shfl_xor_sync(0xffffffffu, val, 16);
        val += __shfl_xor_sync(0xffffffffu, val, 8);
        val += __shfl_xor_sync(0xffffffffu, val, 4);
        val += __shfl_xor_sync(0xffffffffu, val, 2);
        val += __shfl_xor_sync(0xffffffffu, val, 1);
        if (lane == 0) sh_r[w] = val;
        __syncthreads();
        if (tid == 0) {
            float tot = 0.f;
            #pragma unroll
            for (int ww = 0; ww < 32; ++ww) tot += sh_r[ww];
            out[0] = tot;
        }
    }
}

extern "C" void kernel_launch(void* const* d_in, const int* in_sizes, int n_in,
                              void* d_out, int out_size) {
    const int*   x     = (const int*)d_in[0];
    const float* core  = (const float*)d_in[1];
    const float* left  = (const float*)d_in[2];
    const float* right = (const float*)d_in[3];
    float* out = (float*)d_out;
    int F = in_sizes[0];

    tn_chain_kernel<<<NCTA, NTHREADS>>>(x, core, left, right, out, F);
}